// round 12
// baseline (speedup 1.0000x reference)
#include <cuda_runtime.h>
#include <cuda_fp16.h>
#include <stdint.h>

// FlashCrossAttentionV2, two-kernel scheme, all-single-fp16 MMA, M=32/warp:
//  1) cvt_kernel: kv fp32 -> fp16 tile-major pre-swizzled 8KB blocks (once).
//  2) fa_mma12: CTA = 128 thr / 4 warps, TQ=128 (warp owns 32 q-rows = two
//     m16 tiles sharing K/V B-fragments -> ldmatrix traffic halved),
//     TK=64 processed in two 32-key halves (QK -> softmax -> PV per half).
// B=2, Sq=Sk=2048, H=16, D=64, window=(256,256), fp32 I/O.

#define SEQ 2048
#define NH  16
#define DIM 64
#define WIN 256
#define TQ  128
#define TK  64
#define SCALE 0.125f
#define NT  (SEQ / 64)
#define TILE_B 8192

__device__ static unsigned char g_kvh[(size_t)2 * NH * 2 * NT * TILE_B];

// smem: double buffer of (K tile 8KB, V tile 8KB)
#define SM_K 0
#define SM_V 8192
#define SM_BUF 16384
#define SM_TOTAL 32768

typedef uint32_t u32;

static __device__ __forceinline__ u32 smem_u32(const void* p) {
    u32 a;
    asm("{ .reg .u64 t; cvta.to.shared.u64 t, %1; cvt.u32.u64 %0, t; }"
        : "=r"(a) : "l"(p));
    return a;
}
static __device__ __forceinline__ void ldsm4(u32& r0, u32& r1, u32& r2, u32& r3, u32 a) {
    asm volatile("ldmatrix.sync.aligned.m8n8.x4.shared.b16 {%0,%1,%2,%3}, [%4];"
                 : "=r"(r0), "=r"(r1), "=r"(r2), "=r"(r3) : "r"(a));
}
static __device__ __forceinline__ void ldsm4t(u32& r0, u32& r1, u32& r2, u32& r3, u32 a) {
    asm volatile("ldmatrix.sync.aligned.m8n8.x4.trans.shared.b16 {%0,%1,%2,%3}, [%4];"
                 : "=r"(r0), "=r"(r1), "=r"(r2), "=r"(r3) : "r"(a));
}
static __device__ __forceinline__ void mma16816(float* c, u32 a0, u32 a1, u32 a2, u32 a3,
                                                u32 b0, u32 b1) {
    asm volatile("mma.sync.aligned.m16n8k16.row.col.f32.f16.f16.f32 "
                 "{%0,%1,%2,%3},{%4,%5,%6,%7},{%8,%9},{%0,%1,%2,%3};"
                 : "+f"(c[0]), "+f"(c[1]), "+f"(c[2]), "+f"(c[3])
                 : "r"(a0), "r"(a1), "r"(a2), "r"(a3), "r"(b0), "r"(b1));
}
static __device__ __forceinline__ void cpa16(u32 s, const void* g) {
    asm volatile("cp.async.cg.shared.global [%0], [%1], 16;" :: "r"(s), "l"(g));
}
static __device__ __forceinline__ u32 pack_h2(float a, float b) {
    __half2 t = __floats2half2_rn(a, b);
    return *reinterpret_cast<u32*>(&t);
}

// ---------------- pre-pass: convert + swizzle (once) ----------------
__global__ __launch_bounds__(256)
void cvt_kernel(const float* __restrict__ kv)
{
    int idx = blockIdx.x * 256 + threadIdx.x;
    int c    = idx & 15;
    int h    = (idx >> 4) & 15;
    int comp = (idx >> 8) & 1;
    int s    = (idx >> 9) & 2047;
    int b    = idx >> 20;

    float4 f = reinterpret_cast<const float4*>(kv)[idx];
    u32 h0 = pack_h2(f.x, f.y);
    u32 h1 = pack_h2(f.z, f.w);

    int t = s >> 6, r = s & 63;
    size_t byteo = (size_t)(((b * NH + h) * 2 + comp) * NT + t) * TILE_B
                 + r * 128 + (((c >> 1) ^ (r & 7)) * 16) + (c & 1) * 8;
    *reinterpret_cast<uint2*>(g_kvh + byteo) = make_uint2(h0, h1);
}

// ---------------- main kernel ----------------
static __device__ __forceinline__ void stage_tile(u32 dst, const unsigned char* kt,
                                                  const unsigned char* vt, int tid)
{
    #pragma unroll
    for (int it = 0; it < 4; it++) {
        u32 o = it * 2048 + tid * 16;
        cpa16(dst + SM_K + o, kt + o);
        cpa16(dst + SM_V + o, vt + o);
    }
    asm volatile("cp.async.commit_group;");
}

__global__ __launch_bounds__(128, 3)
void fa_mma12(const float* __restrict__ q,
              float* __restrict__ out)
{
    extern __shared__ char smc[];
    const u32 smb = smem_u32(smc);
    const int tid  = threadIdx.x;
    const int w    = tid >> 5;
    const int lane = tid & 31;
    const int q0 = blockIdx.x * TQ;
    const int h  = blockIdx.y;
    const int b  = blockIdx.z;

    const int lr = lane >> 2;
    const int lc = (lane & 3) * 2;
    const int mi    = lane >> 3;
    const int rowin = lane & 7;

    int kt0 = q0 - WIN;      if (kt0 < 0)   kt0 = 0;
    int kt1 = q0 + TQ + WIN; if (kt1 > SEQ) kt1 = SEQ;

    const unsigned char* gK = g_kvh + (size_t)((b * NH + h) * 2 + 0) * NT * TILE_B;
    const unsigned char* gV = g_kvh + (size_t)((b * NH + h) * 2 + 1) * NT * TILE_B;

    {
        int t = kt0 >> 6;
        stage_tile(smb + (t & 1) * SM_BUF,
                   gK + (size_t)t * TILE_B, gV + (size_t)t * TILE_B, tid);
    }

    // ---- Q fragments: two m16 tiles per warp (rows w*32 + mt*16 + ...) ----
    u32 qf[2][4][4];
    #pragma unroll
    for (int mt = 0; mt < 2; mt++) {
        const float* qb  = q + (((size_t)b * SEQ + q0 + w * 32 + mt * 16) * NH + h) * DIM;
        const float* r0p = qb + (size_t)lr * NH * DIM;
        const float* r1p = r0p + (size_t)8 * NH * DIM;
        #pragma unroll
        for (int ks = 0; ks < 4; ks++) {
            float2 f00 = *(const float2*)(r0p + lc + 16 * ks);
            float2 f10 = *(const float2*)(r1p + lc + 16 * ks);
            float2 f01 = *(const float2*)(r0p + lc + 8 + 16 * ks);
            float2 f11 = *(const float2*)(r1p + lc + 8 + 16 * ks);
            qf[mt][ks][0] = pack_h2(f00.x * SCALE, f00.y * SCALE);
            qf[mt][ks][1] = pack_h2(f10.x * SCALE, f10.y * SCALE);
            qf[mt][ks][2] = pack_h2(f01.x * SCALE, f01.y * SCALE);
            qf[mt][ks][3] = pack_h2(f11.x * SCALE, f11.y * SCALE);
        }
    }

    float O[2][8][4];
    #pragma unroll
    for (int mt = 0; mt < 2; mt++)
        #pragma unroll
        for (int nb = 0; nb < 8; nb++)
            #pragma unroll
            for (int e = 0; e < 4; e++) O[mt][nb][e] = 0.f;
    float lsum[2][2] = {{0.f, 0.f}, {0.f, 0.f}};

    for (int k0 = kt0; k0 < kt1; k0 += TK) {
        const int t = k0 >> 6;
        const u32 cur = smb + (t & 1) * SM_BUF;

        asm volatile("cp.async.wait_group 0;" ::: "memory");
        __syncthreads();

        if (k0 + TK < kt1) {
            int tn = t + 1;
            stage_tile(smb + (tn & 1) * SM_BUF,
                       gK + (size_t)tn * TILE_B, gV + (size_t)tn * TILE_B, tid);
        }

        const int dk = k0 - q0;
        const bool edge = (dk < -128) || (dk > 192);

        // ---- process tile in two 32-key halves ----
        #pragma unroll
        for (int kh = 0; kh < 2; kh++) {
            // -- QK: S[2 mt][4 nb][4] over 32 keys --
            float S[2][4][4];
            #pragma unroll
            for (int mt = 0; mt < 2; mt++)
                #pragma unroll
                for (int nb = 0; nb < 4; nb++)
                    #pragma unroll
                    for (int e = 0; e < 4; e++) S[mt][nb][e] = 0.f;

            #pragma unroll
            for (int ks = 0; ks < 4; ks++) {
                #pragma unroll
                for (int np = 0; np < 2; np++) {       // 2 x 16 keys
                    int nbp   = 2 * kh + np;
                    int key   = nbp * 16 + (mi >> 1) * 8 + rowin;
                    int chunk = 2 * ks + (mi & 1);
                    u32 a = cur + SM_K + key * 128 + ((chunk ^ (key & 7)) * 16);
                    u32 h0, h1, h2, h3;
                    ldsm4(h0, h1, h2, h3, a);
                    #pragma unroll
                    for (int mt = 0; mt < 2; mt++) {
                        mma16816(S[mt][2*np],   qf[mt][ks][0], qf[mt][ks][1],
                                 qf[mt][ks][2], qf[mt][ks][3], h0, h1);
                        mma16816(S[mt][2*np+1], qf[mt][ks][0], qf[mt][ks][1],
                                 qf[mt][ks][2], qf[mt][ks][3], h2, h3);
                    }
                }
            }

            // -- softmax + P fragments (2 ksteps of 16 keys) --
            u32 pfr[2][2][4];
            #pragma unroll
            for (int mt = 0; mt < 2; mt++) {
                const int r0g = q0 + w * 32 + mt * 16 + lr;
                #pragma unroll
                for (int ks2 = 0; ks2 < 2; ks2++) {
                    #pragma unroll
                    for (int hf = 0; hf < 2; hf++) {
                        int nb = 2 * ks2 + hf;
                        float p0 = __expf(S[mt][nb][0]);
                        float p1 = __expf(S[mt][nb][1]);
                        float p2 = __expf(S[mt][nb][2]);
                        float p3 = __expf(S[mt][nb][3]);
                        if (edge) {
                            int key = k0 + kh * 32 + nb * 8 + lc;
                            int d0 = key - r0g;
                            int d2 = d0 - 8;
                            if (d0 < -WIN || d0 > WIN)         p0 = 0.f;
                            if (d0 + 1 < -WIN || d0 + 1 > WIN) p1 = 0.f;
                            if (d2 < -WIN || d2 > WIN)         p2 = 0.f;
                            if (d2 + 1 < -WIN || d2 + 1 > WIN) p3 = 0.f;
                        }
                        lsum[mt][0] += p0 + p1;
                        lsum[mt][1] += p2 + p3;
                        pfr[mt][ks2][0 + hf * 2] = pack_h2(p0, p1);
                        pfr[mt][ks2][1 + hf * 2] = pack_h2(p2, p3);
                    }
                }
            }

            // -- PV: O += P*V over this half's 32 keys --
            #pragma unroll
            for (int ks2 = 0; ks2 < 2; ks2++) {
                int kst = 2 * kh + ks2;
                #pragma unroll
                for (int dp = 0; dp < 4; dp++) {
                    int key   = 16 * kst + (mi & 1) * 8 + rowin;
                    int chunk = 2 * dp + (mi >> 1);
                    u32 a = cur + SM_V + key * 128 + ((chunk ^ (key & 7)) * 16);
                    u32 v0, v1, v2, v3;
                    ldsm4t(v0, v1, v2, v3, a);
                    #pragma unroll
                    for (int mt = 0; mt < 2; mt++) {
                        mma16816(O[mt][2*dp],   pfr[mt][ks2][0], pfr[mt][ks2][1],
                                 pfr[mt][ks2][2], pfr[mt][ks2][3], v0, v1);
                        mma16816(O[mt][2*dp+1], pfr[mt][ks2][0], pfr[mt][ks2][1],
                                 pfr[mt][ks2][2], pfr[mt][ks2][3], v2, v3);
                    }
                }
            }
        }
    }

    // ---- row sums (quad reduce), normalize, store ----
    #pragma unroll
    for (int mt = 0; mt < 2; mt++) {
        float l0 = lsum[mt][0], l1 = lsum[mt][1];
        l0 += __shfl_xor_sync(0xffffffffu, l0, 1);
        l0 += __shfl_xor_sync(0xffffffffu, l0, 2);
        l1 += __shfl_xor_sync(0xffffffffu, l1, 1);
        l1 += __shfl_xor_sync(0xffffffffu, l1, 2);
        const float i0 = 1.0f / l0;
        const float i1 = 1.0f / l1;

        float* ob  = out + (((size_t)b * SEQ + q0 + w * 32 + mt * 16 + lr) * NH + h) * DIM + lc;
        float* ob8 = ob + (size_t)8 * NH * DIM;
        #pragma unroll
        for (int nb = 0; nb < 8; nb++) {
            *(float2*)(ob + nb * 8)  = make_float2(O[mt][nb][0] * i0, O[mt][nb][1] * i0);
            *(float2*)(ob8 + nb * 8) = make_float2(O[mt][nb][2] * i1, O[mt][nb][3] * i1);
        }
    }
}

extern "C" void kernel_launch(void* const* d_in, const int* in_sizes, int n_in,
                              void* d_out, int out_size)
{
    const float* q  = (const float*)d_in[0];
    const float* kv = (const float*)d_in[1];
    float* out = (float*)d_out;

    int B = in_sizes[0] / (SEQ * NH * DIM);

    int nblk = (B * SEQ * 2 * NH * (DIM / 4)) / 256;
    cvt_kernel<<<nblk, 256>>>(kv);

    cudaFuncSetAttribute(fa_mma12,
                         cudaFuncAttributeMaxDynamicSharedMemorySize, SM_TOTAL);
    dim3 grid(SEQ / TQ, NH, B);
    fa_mma12<<<grid, 128, SM_TOTAL>>>(q, out);
}

// round 13
// speedup vs baseline: 1.0019x; 1.0019x over previous
#include <cuda_runtime.h>
#include <cuda_fp16.h>
#include <stdint.h>

// FlashCrossAttentionV2, two-kernel scheme, all-single-fp16 MMA.
//  1) cvt_kernel: kv fp32 -> fp16 tile-major pre-swizzled 8KB blocks (once).
//  2) fa_mma13: CTA = 64 threads (2 warps), TQ=64; each warp owns 32 q-rows
//     (two m16 tiles sharing K/V B-fragments -> halved ldmatrix traffic),
//     6 CTAs/SM. TK=64 in two 32-key halves (QK -> softmax -> PV per half).
// B=2, Sq=Sk=2048, H=16, D=64, window=(256,256), fp32 I/O.

#define SEQ 2048
#define NH  16
#define DIM 64
#define WIN 256
#define TQ  64
#define TK  64
#define SCALE 0.125f
#define NT  (SEQ / 64)
#define TILE_B 8192

__device__ static unsigned char g_kvh[(size_t)2 * NH * 2 * NT * TILE_B];

// smem: double buffer of (K tile 8KB, V tile 8KB)
#define SM_K 0
#define SM_V 8192
#define SM_BUF 16384
#define SM_TOTAL 32768

typedef uint32_t u32;

static __device__ __forceinline__ u32 smem_u32(const void* p) {
    u32 a;
    asm("{ .reg .u64 t; cvta.to.shared.u64 t, %1; cvt.u32.u64 %0, t; }"
        : "=r"(a) : "l"(p));
    return a;
}
static __device__ __forceinline__ void ldsm4(u32& r0, u32& r1, u32& r2, u32& r3, u32 a) {
    asm volatile("ldmatrix.sync.aligned.m8n8.x4.shared.b16 {%0,%1,%2,%3}, [%4];"
                 : "=r"(r0), "=r"(r1), "=r"(r2), "=r"(r3) : "r"(a));
}
static __device__ __forceinline__ void ldsm4t(u32& r0, u32& r1, u32& r2, u32& r3, u32 a) {
    asm volatile("ldmatrix.sync.aligned.m8n8.x4.trans.shared.b16 {%0,%1,%2,%3}, [%4];"
                 : "=r"(r0), "=r"(r1), "=r"(r2), "=r"(r3) : "r"(a));
}
static __device__ __forceinline__ void mma16816(float* c, u32 a0, u32 a1, u32 a2, u32 a3,
                                                u32 b0, u32 b1) {
    asm volatile("mma.sync.aligned.m16n8k16.row.col.f32.f16.f16.f32 "
                 "{%0,%1,%2,%3},{%4,%5,%6,%7},{%8,%9},{%0,%1,%2,%3};"
                 : "+f"(c[0]), "+f"(c[1]), "+f"(c[2]), "+f"(c[3])
                 : "r"(a0), "r"(a1), "r"(a2), "r"(a3), "r"(b0), "r"(b1));
}
static __device__ __forceinline__ void cpa16(u32 s, const void* g) {
    asm volatile("cp.async.cg.shared.global [%0], [%1], 16;" :: "r"(s), "l"(g));
}
static __device__ __forceinline__ u32 pack_h2(float a, float b) {
    __half2 t = __floats2half2_rn(a, b);
    return *reinterpret_cast<u32*>(&t);
}

// ---------------- pre-pass: convert + swizzle (once) ----------------
__global__ __launch_bounds__(256)
void cvt_kernel(const float* __restrict__ kv)
{
    int idx = blockIdx.x * 256 + threadIdx.x;
    int c    = idx & 15;
    int h    = (idx >> 4) & 15;
    int comp = (idx >> 8) & 1;
    int s    = (idx >> 9) & 2047;
    int b    = idx >> 20;

    float4 f = reinterpret_cast<const float4*>(kv)[idx];
    u32 h0 = pack_h2(f.x, f.y);
    u32 h1 = pack_h2(f.z, f.w);

    int t = s >> 6, r = s & 63;
    size_t byteo = (size_t)(((b * NH + h) * 2 + comp) * NT + t) * TILE_B
                 + r * 128 + (((c >> 1) ^ (r & 7)) * 16) + (c & 1) * 8;
    *reinterpret_cast<uint2*>(g_kvh + byteo) = make_uint2(h0, h1);
}

// ---------------- main kernel ----------------
static __device__ __forceinline__ void stage_tile(u32 dst, const unsigned char* kt,
                                                  const unsigned char* vt, int tid)
{
    #pragma unroll
    for (int it = 0; it < 8; it++) {
        u32 o = it * 1024 + tid * 16;
        cpa16(dst + SM_K + o, kt + o);
        cpa16(dst + SM_V + o, vt + o);
    }
    asm volatile("cp.async.commit_group;");
}

__global__ __launch_bounds__(64, 6)
void fa_mma13(const float* __restrict__ q,
              float* __restrict__ out)
{
    extern __shared__ char smc[];
    const u32 smb = smem_u32(smc);
    const int tid  = threadIdx.x;
    const int w    = tid >> 5;      // 0..1
    const int lane = tid & 31;
    const int q0 = blockIdx.x * TQ;
    const int h  = blockIdx.y;
    const int b  = blockIdx.z;

    const int lr = lane >> 2;
    const int lc = (lane & 3) * 2;
    const int mi    = lane >> 3;
    const int rowin = lane & 7;

    int kt0 = q0 - WIN;      if (kt0 < 0)   kt0 = 0;
    int kt1 = q0 + TQ + WIN; if (kt1 > SEQ) kt1 = SEQ;

    const unsigned char* gK = g_kvh + (size_t)((b * NH + h) * 2 + 0) * NT * TILE_B;
    const unsigned char* gV = g_kvh + (size_t)((b * NH + h) * 2 + 1) * NT * TILE_B;

    {
        int t = kt0 >> 6;
        stage_tile(smb + (t & 1) * SM_BUF,
                   gK + (size_t)t * TILE_B, gV + (size_t)t * TILE_B, tid);
    }

    // ---- Q fragments: two m16 tiles per warp (rows q0 + w*32 + mt*16 ...) ----
    u32 qf[2][4][4];
    #pragma unroll
    for (int mt = 0; mt < 2; mt++) {
        const float* qb  = q + (((size_t)b * SEQ + q0 + w * 32 + mt * 16) * NH + h) * DIM;
        const float* r0p = qb + (size_t)lr * NH * DIM;
        const float* r1p = r0p + (size_t)8 * NH * DIM;
        #pragma unroll
        for (int ks = 0; ks < 4; ks++) {
            float2 f00 = *(const float2*)(r0p + lc + 16 * ks);
            float2 f10 = *(const float2*)(r1p + lc + 16 * ks);
            float2 f01 = *(const float2*)(r0p + lc + 8 + 16 * ks);
            float2 f11 = *(const float2*)(r1p + lc + 8 + 16 * ks);
            qf[mt][ks][0] = pack_h2(f00.x * SCALE, f00.y * SCALE);
            qf[mt][ks][1] = pack_h2(f10.x * SCALE, f10.y * SCALE);
            qf[mt][ks][2] = pack_h2(f01.x * SCALE, f01.y * SCALE);
            qf[mt][ks][3] = pack_h2(f11.x * SCALE, f11.y * SCALE);
        }
    }

    float O[2][8][4];
    #pragma unroll
    for (int mt = 0; mt < 2; mt++)
        #pragma unroll
        for (int nb = 0; nb < 8; nb++)
            #pragma unroll
            for (int e = 0; e < 4; e++) O[mt][nb][e] = 0.f;
    float lsum[2][2] = {{0.f, 0.f}, {0.f, 0.f}};

    for (int k0 = kt0; k0 < kt1; k0 += TK) {
        const int t = k0 >> 6;
        const u32 cur = smb + (t & 1) * SM_BUF;

        asm volatile("cp.async.wait_group 0;" ::: "memory");
        __syncthreads();

        if (k0 + TK < kt1) {
            int tn = t + 1;
            stage_tile(smb + (tn & 1) * SM_BUF,
                       gK + (size_t)tn * TILE_B, gV + (size_t)tn * TILE_B, tid);
        }

        const int dk = k0 - q0;
        const bool edge = (dk == -WIN) || (dk == WIN);

        // ---- process tile in two 32-key halves ----
        #pragma unroll
        for (int kh = 0; kh < 2; kh++) {
            // -- QK: S[2 mt][4 nb][4] over 32 keys --
            float S[2][4][4];
            #pragma unroll
            for (int mt = 0; mt < 2; mt++)
                #pragma unroll
                for (int nb = 0; nb < 4; nb++)
                    #pragma unroll
                    for (int e = 0; e < 4; e++) S[mt][nb][e] = 0.f;

            #pragma unroll
            for (int ks = 0; ks < 4; ks++) {
                #pragma unroll
                for (int np = 0; np < 2; np++) {       // 2 x 16 keys
                    int nbp   = 2 * kh + np;
                    int key   = nbp * 16 + (mi >> 1) * 8 + rowin;
                    int chunk = 2 * ks + (mi & 1);
                    u32 a = cur + SM_K + key * 128 + ((chunk ^ (key & 7)) * 16);
                    u32 h0, h1, h2, h3;
                    ldsm4(h0, h1, h2, h3, a);
                    #pragma unroll
                    for (int mt = 0; mt < 2; mt++) {
                        mma16816(S[mt][2*np],   qf[mt][ks][0], qf[mt][ks][1],
                                 qf[mt][ks][2], qf[mt][ks][3], h0, h1);
                        mma16816(S[mt][2*np+1], qf[mt][ks][0], qf[mt][ks][1],
                                 qf[mt][ks][2], qf[mt][ks][3], h2, h3);
                    }
                }
            }

            // -- softmax + P fragments (2 ksteps of 16 keys) --
            u32 pfr[2][2][4];
            #pragma unroll
            for (int mt = 0; mt < 2; mt++) {
                const int r0g = q0 + w * 32 + mt * 16 + lr;
                #pragma unroll
                for (int ks2 = 0; ks2 < 2; ks2++) {
                    #pragma unroll
                    for (int hf = 0; hf < 2; hf++) {
                        int nb = 2 * ks2 + hf;
                        float p0 = __expf(S[mt][nb][0]);
                        float p1 = __expf(S[mt][nb][1]);
                        float p2 = __expf(S[mt][nb][2]);
                        float p3 = __expf(S[mt][nb][3]);
                        if (edge) {
                            int key = k0 + kh * 32 + nb * 8 + lc;
                            int d0 = key - r0g;
                            int d2 = d0 - 8;
                            if (d0 < -WIN || d0 > WIN)         p0 = 0.f;
                            if (d0 + 1 < -WIN || d0 + 1 > WIN) p1 = 0.f;
                            if (d2 < -WIN || d2 > WIN)         p2 = 0.f;
                            if (d2 + 1 < -WIN || d2 + 1 > WIN) p3 = 0.f;
                        }
                        lsum[mt][0] += p0 + p1;
                        lsum[mt][1] += p2 + p3;
                        pfr[mt][ks2][0 + hf * 2] = pack_h2(p0, p1);
                        pfr[mt][ks2][1 + hf * 2] = pack_h2(p2, p3);
                    }
                }
            }

            // -- PV: O += P*V over this half's 32 keys --
            #pragma unroll
            for (int ks2 = 0; ks2 < 2; ks2++) {
                int kst = 2 * kh + ks2;
                #pragma unroll
                for (int dp = 0; dp < 4; dp++) {
                    int key   = 16 * kst + (mi & 1) * 8 + rowin;
                    int chunk = 2 * dp + (mi >> 1);
                    u32 a = cur + SM_V + key * 128 + ((chunk ^ (key & 7)) * 16);
                    u32 v0, v1, v2, v3;
                    ldsm4t(v0, v1, v2, v3, a);
                    #pragma unroll
                    for (int mt = 0; mt < 2; mt++) {
                        mma16816(O[mt][2*dp],   pfr[mt][ks2][0], pfr[mt][ks2][1],
                                 pfr[mt][ks2][2], pfr[mt][ks2][3], v0, v1);
                        mma16816(O[mt][2*dp+1], pfr[mt][ks2][0], pfr[mt][ks2][1],
                                 pfr[mt][ks2][2], pfr[mt][ks2][3], v2, v3);
                    }
                }
            }
        }
    }

    // ---- row sums (quad reduce), normalize, store ----
    #pragma unroll
    for (int mt = 0; mt < 2; mt++) {
        float l0 = lsum[mt][0], l1 = lsum[mt][1];
        l0 += __shfl_xor_sync(0xffffffffu, l0, 1);
        l0 += __shfl_xor_sync(0xffffffffu, l0, 2);
        l1 += __shfl_xor_sync(0xffffffffu, l1, 1);
        l1 += __shfl_xor_sync(0xffffffffu, l1, 2);
        const float i0 = 1.0f / l0;
        const float i1 = 1.0f / l1;

        float* ob  = out + (((size_t)b * SEQ + q0 + w * 32 + mt * 16 + lr) * NH + h) * DIM + lc;
        float* ob8 = ob + (size_t)8 * NH * DIM;
        #pragma unroll
        for (int nb = 0; nb < 8; nb++) {
            *(float2*)(ob + nb * 8)  = make_float2(O[mt][nb][0] * i0, O[mt][nb][1] * i0);
            *(float2*)(ob8 + nb * 8) = make_float2(O[mt][nb][2] * i1, O[mt][nb][3] * i1);
        }
    }
}

extern "C" void kernel_launch(void* const* d_in, const int* in_sizes, int n_in,
                              void* d_out, int out_size)
{
    const float* q  = (const float*)d_in[0];
    const float* kv = (const float*)d_in[1];
    float* out = (float*)d_out;

    int B = in_sizes[0] / (SEQ * NH * DIM);

    int nblk = (B * SEQ * 2 * NH * (DIM / 4)) / 256;
    cvt_kernel<<<nblk, 256>>>(kv);

    cudaFuncSetAttribute(fa_mma13,
                         cudaFuncAttributeMaxDynamicSharedMemorySize, SM_TOTAL);
    dim3 grid(SEQ / TQ, NH, B);
    fa_mma13<<<grid, 64, SM_TOTAL>>>(q, out);
}